// round 10
// baseline (speedup 1.0000x reference)
#include <cuda_runtime.h>

typedef unsigned long long u64;

#define NQ    12
#define DEPTH 4
#define NPAR  144
#define THREADS 512

__device__ __forceinline__ u64 f2fma(u64 a, u64 b, u64 c) {
    u64 d; asm("fma.rn.f32x2 %0,%1,%2,%3;" : "=l"(d) : "l"(a), "l"(b), "l"(c)); return d;
}
__device__ __forceinline__ u64 f2mul(u64 a, u64 b) {
    u64 d; asm("mul.rn.f32x2 %0,%1,%2;" : "=l"(d) : "l"(a), "l"(b)); return d;
}
__device__ __forceinline__ u64 pk(float lo, float hi) {
    u64 r; asm("mov.b64 %0,{%1,%2};" : "=l"(r) : "f"(lo), "f"(hi)); return r;
}
__device__ __forceinline__ void upk(u64 v, float& lo, float& hi) {
    asm("mov.b64 {%0,%1},%2;" : "=f"(lo), "=f"(hi) : "l"(v));
}
__device__ __forceinline__ u64 f2swap(u64 v) {
    float lo, hi; upk(v, lo, hi); return pk(hi, lo);
}

struct c2 { float r, i; };
__device__ __forceinline__ c2 cmul(c2 a, c2 b) {
    c2 o; o.r = a.r * b.r - a.i * b.i; o.i = a.r * b.i + a.i * b.r; return o;
}

// CNOT-ring linear map (reference gate order): suffix parity
__device__ __forceinline__ int perm12(int s) {
    int d = s;
    #pragma unroll
    for (int q = 0; q < 12; q++) {
        int bc = 11 - q, bt = 11 - ((q + 1) % 12);
        d ^= ((d >> bc) & 1) << bt;
    }
    return d;
}
// physical float swizzle: F(i) = i ^ (i5<<1) ^ (i6<<2) ^ (i7<<3) ^ (i6<<4)
__device__ __forceinline__ int Fnew(int i) {
    return i ^ (((i >> 5) & 1) << 1) ^ (((i >> 6) & 1) << 2)
             ^ (((i >> 7) & 1) << 3) ^ (((i >> 6) & 1) << 4);
}

#define LOADC(gi)                                                     \
    const u64* rec = gpk + (gi) * 12;                                 \
    ulonglong2 q01 = *(const ulonglong2*)(rec);                       \
    ulonglong2 q23 = *(const ulonglong2*)(rec + 2);                   \
    ulonglong2 q45 = *(const ulonglong2*)(rec + 4);                   \
    u64 PX = q01.x, PY = q01.y, NY = q23.x, PZ = q23.y;               \
    u64 NZ = q45.x, PW = q45.y, NW = rec[6];

// swap-form gate on the pack lane (4 packed regs)
#define PACK_GATE(gi)                                                 \
    {                                                                 \
        const u64* rec = gpk + (gi) * 12;                             \
        u64 PX = rec[0], PWv = rec[5], NWv = rec[6];                  \
        ulonglong2 mm = *(const ulonglong2*)(rec + 8);                \
        u64 MY = mm.x, MYr = mm.y, MZ = rec[10];                      \
        _Pragma("unroll")                                             \
        for (int p = 0; p < 4; p++) {                                 \
            u64 R = Re[p], I = Im[p];                                 \
            u64 Rs = f2swap(R), Is = f2swap(I);                       \
            Re[p] = f2fma(NWv, Is, f2fma(MZ, Rs, f2fma(MY,  I, f2mul(PX, R)))); \
            Im[p] = f2fma(PWv, Rs, f2fma(MZ, Is, f2fma(MYr, R, f2mul(PX, I)))); \
        }                                                             \
    }

// register-pair gate over reg-bit mask (1,2)
#define REGPAIR_GATE(gi, mask)                                        \
    {                                                                 \
        LOADC(gi)                                                     \
        _Pragma("unroll")                                             \
        for (int p0 = 0; p0 < 4; p0++) {                              \
            if (p0 & (mask)) continue;                                \
            const int p1 = p0 | (mask);                               \
            u64 aR = Re[p0], aI = Im[p0], bR = Re[p1], bI = Im[p1];   \
            Re[p0] = f2fma(NW, bI, f2fma(PZ, bR, f2fma(NY, aI, f2mul(PX, aR)))); \
            Im[p0] = f2fma(PW, bR, f2fma(PZ, bI, f2fma(PY, aR, f2mul(PX, aI)))); \
            Re[p1] = f2fma(NW, aI, f2fma(NZ, aR, f2fma(PY, bI, f2mul(PX, bR)))); \
            Im[p1] = f2fma(PW, aR, f2fma(NZ, aI, f2fma(NY, bR, f2mul(PX, bI)))); \
        }                                                             \
    }

__global__ __launch_bounds__(THREADS, 2)
void qgen_kernel(const float* __restrict__ noise,
                 const float* __restrict__ W1, const float* __restrict__ b1,
                 const float* __restrict__ W2, const float* __restrict__ b2,
                 const float* __restrict__ W3, const float* __restrict__ b3,
                 const float* __restrict__ W4, const float* __restrict__ b4,
                 float* __restrict__ out)
{
    __shared__ __align__(16) u64 exR64[2048];
    __shared__ __align__(16) u64 exI64[2048];
    __shared__ __align__(16) u64 gpk[48 * 12];
    __shared__ float2 s_v[12][2];
    __shared__ float s_nz[12];
    __shared__ float s_h[64];
    __shared__ float s_par[NPAR];
    __shared__ float s_meas[12];
    __shared__ float s_wsum[16][12];
    __shared__ float s_h2[64];

    float* exRf = (float*)exR64;
    float* exIf = (float*)exI64;

    const int t   = threadIdx.x;
    const int bId = blockIdx.x;

    if (t < 12) s_nz[t] = noise[bId * 12 + t];
    __syncthreads();

    // ---- MLP1 ----
    if (t < 64) {
        float acc = b1[t];
        #pragma unroll
        for (int m = 0; m < 12; m++) acc += s_nz[m] * W1[m * 64 + t];
        s_h[t] = tanhf(acc);
    }
    __syncthreads();

    // ---- MLP2 ----
    if (t < NPAR) {
        float acc = b2[t];
        #pragma unroll 8
        for (int j = 0; j < 64; j++) acc += s_h[j] * W2[j * NPAR + t];
        s_par[t] = acc;
    }
    __syncthreads();

    // ---- per-gate SU(2): U = RZ(c)RY(b)RX(a) = [[gx+igy, gz+igw],[-(gz-igw), gx-igy]]
    if (t < 48) {
        float a = s_par[t * 3 + 0], b = s_par[t * 3 + 1], c = s_par[t * 3 + 2];
        float ca, sa, cb, sb, cc, sc;
        sincosf(0.5f * a, &sa, &ca);
        sincosf(0.5f * b, &sb, &cb);
        sincosf(0.5f * c, &sc, &cc);
        float x = cb * ca, y = sb * sa, z = sb * ca, w = cb * sa;
        float gx =  cc * x + sc * y;
        float gy =  cc * y - sc * x;
        float gz = -(cc * z + sc * w);
        float gw =  sc * z - cc * w;
        u64* r = gpk + t * 12;
        r[0]  = pk(gx, gx);  r[1] = pk(gy, gy);  r[2] = pk(-gy, -gy);
        r[3]  = pk(gz, gz);  r[4] = pk(-gz, -gz);
        r[5]  = pk(gw, gw);  r[6] = pk(-gw, -gw);
        r[8]  = pk(-gy, gy); r[9] = pk(gy, -gy); r[10] = pk(gz, -gz);
        if (t < 12) {   // layer-0: U|0> = (gx+igy, -(gz-igw))
            s_v[t][0] = make_float2(gx, gy);
            s_v[t][1] = make_float2(-gz, gw);
        }
    }

    // ---- per-thread addresses (t = 9 bits) ----
    // Layout A: i=(t<<3)|(r1<<2)|(r0<<1)|k ; u64 unit = UA ^ rA
    const int UA = (t << 2) ^ ((t >> 2) & 1) ^ (((t >> 3) & 1) << 1)
                 ^ (((t >> 4) & 1) << 2) ^ (((t >> 3) & 1) << 3);
    // Layout C: i=((t>>3)<<6)|(r1<<5)|(r0<<4)|(k<<3)|(t&7)
    const int FC = (((t >> 3) << 6) | (t & 7)) ^ (((t >> 3) & 1) << 2)
                 ^ (((t >> 4) & 1) << 3) ^ (((t >> 3) & 1) << 4);
    // Layout D: i=((t>>6)<<9)|(r1<<8)|(r0<<7)|(k<<6)|(t&63)
    const int FD = (((t >> 6) << 9) | (t & 63)) ^ (((t >> 5) & 1) << 1);
    // Layout B: i=(r1<<11)|(r0<<10)|(k<<9)|t
    const int FB = Fnew(t);
    // perm scatter base
    const int pFP = Fnew(perm12(t));

    __syncthreads();   // gpk + s_v visible

    // ---- layer 0 (gates + first ring) synthesized directly in layout A ----
    u64 Re[4], Im[4];
    {
        #define LV(q, e) ({ float2 f = s_v[q][(e) & 1]; c2 z; z.r = f.x; z.i = f.y; z; })
        c2 base = cmul(cmul(cmul(LV(2, (t >> 6) ^ (t >> 7)), LV(3, (t >> 5) ^ (t >> 6))),
                            cmul(LV(4, (t >> 4) ^ (t >> 5)), LV(5, (t >> 3) ^ (t >> 4)))),
                       cmul(cmul(LV(6, (t >> 2) ^ (t >> 3)), LV(7, (t >> 1) ^ (t >> 2))),
                            LV(8, t ^ (t >> 1))));
        const int t0 = t & 1, t8 = (t >> 8) & 1, t78 = ((t >> 7) ^ (t >> 8)) & 1;
        c2 W0 = cmul(LV(0, t8),     LV(1, t78));       // k=0
        c2 W1v = cmul(LV(0, t8 ^ 1), LV(1, t78 ^ 1));  // k=1
        // T[k][r0] = v11[k^r0] * W_k
        c2 T00 = cmul(LV(11, 0), W0);
        c2 T01 = cmul(LV(11, 1), W0);
        c2 T10 = cmul(LV(11, 1), W1v);
        c2 T11 = cmul(LV(11, 0), W1v);
        // B_{r1} = base * v9[r1 ^ t0]
        c2 B0 = cmul(base, LV(9, t0));
        c2 B1 = cmul(base, LV(9, t0 ^ 1));
        // C[rA] = B_{r1} * v10[r0^r1]
        c2 C0 = cmul(B0, LV(10, 0));   // rA=0: r1=0,r0=0
        c2 C1 = cmul(B0, LV(10, 1));   // rA=1: r1=0,r0=1
        c2 C2 = cmul(B1, LV(10, 1));   // rA=2: r1=1,r0=0
        c2 C3 = cmul(B1, LV(10, 0));   // rA=3: r1=1,r0=1
        #undef LV
        c2 lo, hi;
        lo = cmul(C0, T00); hi = cmul(C0, T10);
        Re[0] = pk(lo.r, hi.r); Im[0] = pk(lo.i, hi.i);
        lo = cmul(C1, T01); hi = cmul(C1, T11);
        Re[1] = pk(lo.r, hi.r); Im[1] = pk(lo.i, hi.i);
        lo = cmul(C2, T00); hi = cmul(C2, T10);
        Re[2] = pk(lo.r, hi.r); Im[2] = pk(lo.i, hi.i);
        lo = cmul(C3, T01); hi = cmul(C3, T11);
        Re[3] = pk(lo.r, hi.r); Im[3] = pk(lo.i, hi.i);
    }

    const int rcOff[4] = {0x00, 0x10, 0x22, 0x32};
    const int rdOff[4] = {0x000, 0x088, 0x100, 0x188};
    const int rbOff[4] = {0x000, 0x400, 0x800, 0xC00};

    // ---- layers 1..3 : A -> C -> D -> B (-> perm) ----
    #pragma unroll 1
    for (int l = 1; l < DEPTH; l++) {
        // A: q11 pack, q10 mask1, q9 mask2
        PACK_GATE(l * 12 + 11)
        REGPAIR_GATE(l * 12 + 10, 1)
        REGPAIR_GATE(l * 12 + 9, 2)

        // exchange A -> C
        __syncthreads();
        #pragma unroll
        for (int r = 0; r < 4; r++) {
            exR64[UA ^ r] = Re[r];
            exI64[UA ^ r] = Im[r];
        }
        __syncthreads();
        #pragma unroll
        for (int r = 0; r < 4; r++) {
            const int a0 = FC ^ rcOff[r];
            const int a1 = a0 ^ 8;
            Re[r] = pk(exRf[a0], exRf[a1]);
            Im[r] = pk(exIf[a0], exIf[a1]);
        }

        // C: q8 pack, q7 mask1, q6 mask2
        PACK_GATE(l * 12 + 8)
        REGPAIR_GATE(l * 12 + 7, 1)
        REGPAIR_GATE(l * 12 + 6, 2)

        // exchange C -> D
        __syncthreads();
        #pragma unroll
        for (int r = 0; r < 4; r++) {
            float lo, hi, li, hii;
            upk(Re[r], lo, hi); upk(Im[r], li, hii);
            const int a0 = FC ^ rcOff[r];
            const int a1 = a0 ^ 8;
            exRf[a0] = lo;  exIf[a0] = li;
            exRf[a1] = hi;  exIf[a1] = hii;
        }
        __syncthreads();
        #pragma unroll
        for (int r = 0; r < 4; r++) {
            const int a0 = FD ^ rdOff[r];
            const int a1 = a0 ^ 0x54;
            Re[r] = pk(exRf[a0], exRf[a1]);
            Im[r] = pk(exIf[a0], exIf[a1]);
        }

        // D: q5 pack, q4 mask1, q3 mask2
        PACK_GATE(l * 12 + 5)
        REGPAIR_GATE(l * 12 + 4, 1)
        REGPAIR_GATE(l * 12 + 3, 2)

        // exchange D -> B
        __syncthreads();
        #pragma unroll
        for (int r = 0; r < 4; r++) {
            float lo, hi, li, hii;
            upk(Re[r], lo, hi); upk(Im[r], li, hii);
            const int a0 = FD ^ rdOff[r];
            const int a1 = a0 ^ 0x54;
            exRf[a0] = lo;  exIf[a0] = li;
            exRf[a1] = hi;  exIf[a1] = hii;
        }
        __syncthreads();
        #pragma unroll
        for (int r = 0; r < 4; r++) {
            const int a0 = FB ^ rbOff[r];
            const int a1 = a0 ^ 0x200;
            Re[r] = pk(exRf[a0], exRf[a1]);
            Im[r] = pk(exIf[a0], exIf[a1]);
        }

        // B: q2 pack, q1 mask1, q0 mask2
        PACK_GATE(l * 12 + 2)
        REGPAIR_GATE(l * 12 + 1, 1)
        REGPAIR_GATE(l * 12 + 0, 2)

        if (l == DEPTH - 1) break;   // final ring folded into measurement signs

        // perm scatter B -> A
        __syncthreads();
        #pragma unroll
        for (int r = 0; r < 4; r++) {
            float lo, hi, li, hii;
            upk(Re[r], lo, hi); upk(Im[r], li, hii);
            const int rk = ((r & 1) << 10) | ((r >> 1) << 11);
            const int a0 = pFP ^ Fnew(perm12(rk));
            const int a1 = pFP ^ Fnew(perm12(rk | 0x200));
            exRf[a0] = lo;  exIf[a0] = li;
            exRf[a1] = hi;  exIf[a1] = hii;
        }
        __syncthreads();
        #pragma unroll
        for (int r = 0; r < 4; r++) {
            Re[r] = exR64[UA ^ r];
            Im[r] = exI64[UA ^ r];
        }
    }

    // ---- <Z_q> in layout B; final ring folded into suffix-parity signs ----
    // s = (r1<<11)|(r0<<10)|(k<<9)|t ; d_b = parity(s_b..s_11)
    float U0 = 0.f, U1 = 0.f, U2 = 0.f;
    #pragma unroll
    for (int r = 0; r < 4; r++) {
        u64 p2 = f2fma(Im[r], Im[r], f2mul(Re[r], Re[r]));
        float pl, ph; upk(p2, pl, ph);
        float sm = pl + ph, df = pl - ph;
        U0 += (r & 1) ? -df : df;                   // q0: s10 part, df (s9=k)
        float s2 = (__popc(r & 3) & 1) ? -1.f : 1.f; // r0^r1
        U1 += s2 * sm;                               // q1: s10^s11
        U2 += s2 * df;                               // q2..q11 base: k^r0^r1
    }
    float c[12];
    c[0] = (__popc(t & 0x1FF) & 1) ? -U0 : U0;
    c[1] = U1;
    c[2] = U2;
    {
        const int masks[9] = {0x100, 0x180, 0x1C0, 0x1E0, 0x1F0,
                              0x1F8, 0x1FC, 0x1FE, 0x1FF};
        #pragma unroll
        for (int q = 3; q < 12; q++)
            c[q] = (__popc(t & masks[q - 3]) & 1) ? -U2 : U2;
    }

    #pragma unroll
    for (int s = 16; s >= 1; s >>= 1) {
        #pragma unroll
        for (int q = 0; q < 12; q++)
            c[q] += __shfl_xor_sync(0xffffffffu, c[q], s);
    }
    const int warp = t >> 5, lane = t & 31;
    if (lane == 0) {
        #pragma unroll
        for (int q = 0; q < 12; q++) s_wsum[warp][q] = c[q];
    }
    __syncthreads();
    if (t < 12) {
        float m = 0.f;
        #pragma unroll
        for (int w = 0; w < 16; w++) m += s_wsum[w][t];
        s_meas[t] = m;
    }
    __syncthreads();

    // ---- MLP3 ----
    if (t < 64) {
        float acc = b3[t];
        #pragma unroll
        for (int q = 0; q < 12; q++) acc += s_meas[q] * W3[q * 64 + t];
        s_h2[t] = tanhf(acc);
    }
    __syncthreads();

    // ---- out ----
    if (t < 2) {
        float acc = b4[t];
        #pragma unroll 8
        for (int j = 0; j < 64; j++) acc += s_h2[j] * W4[j * 2 + t];
        out[bId * 2 + t] = acc;
    }
}

extern "C" void kernel_launch(void* const* d_in, const int* in_sizes, int n_in,
                              void* d_out, int out_size)
{
    (void)n_in; (void)out_size;
    const float* noise = (const float*)d_in[0];
    const float* W1    = (const float*)d_in[1];
    const float* b1    = (const float*)d_in[2];
    const float* W2    = (const float*)d_in[3];
    const float* b2    = (const float*)d_in[4];
    const float* W3    = (const float*)d_in[5];
    const float* b3    = (const float*)d_in[6];
    const float* W4    = (const float*)d_in[7];
    const float* b4    = (const float*)d_in[8];
    float* out = (float*)d_out;

    const int B = in_sizes[0] / NQ;
    qgen_kernel<<<B, THREADS>>>(noise, W1, b1, W2, b2, W3, b3, W4, b4, out);
}

// round 11
// speedup vs baseline: 1.1958x; 1.1958x over previous
#include <cuda_runtime.h>

typedef unsigned long long u64;

#define NQ    12
#define DEPTH 4
#define NPAR  144
#define THREADS 256

// ---------- f32x2 packed helpers ----------
__device__ __forceinline__ u64 f2fma(u64 a, u64 b, u64 c) {
    u64 d; asm("fma.rn.f32x2 %0,%1,%2,%3;" : "=l"(d) : "l"(a), "l"(b), "l"(c)); return d;
}
__device__ __forceinline__ u64 f2mul(u64 a, u64 b) {
    u64 d; asm("mul.rn.f32x2 %0,%1,%2;" : "=l"(d) : "l"(a), "l"(b)); return d;
}
__device__ __forceinline__ u64 pk(float lo, float hi) {
    u64 r; asm("mov.b64 %0,{%1,%2};" : "=l"(r) : "f"(lo), "f"(hi)); return r;
}
__device__ __forceinline__ void upk(u64 v, float& lo, float& hi) {
    asm("mov.b64 {%0,%1},%2;" : "=f"(lo), "=f"(hi) : "l"(v));
}
__device__ __forceinline__ u64 f2swap(u64 v) {
    float lo, hi; upk(v, lo, hi); return pk(hi, lo);
}

struct c2 { float r, i; };
__device__ __forceinline__ c2 cmul(c2 a, c2 b) {
    c2 o; o.r = a.r * b.r - a.i * b.i; o.i = a.r * b.i + a.i * b.r; return o;
}
__device__ __forceinline__ float2 cm2(float2 a, float2 b) {
    return make_float2(a.x * b.x - a.y * b.y, a.x * b.y + a.y * b.x);
}

// ---------- CNOT-ring permutation (reference gate order) ----------
__device__ __forceinline__ int perm12(int s) {
    int d = s;
    #pragma unroll
    for (int q = 0; q < 12; q++) {
        int bc = 11 - q, bt = 11 - ((q + 1) % 12);
        d ^= ((d >> bc) & 1) << bt;
    }
    return d;
}
__device__ __forceinline__ int laddr(int d) {
    return ((d >> 5) << 7) | ((((d >> 1) & 15) ^ ((d >> 5) & 15)) << 3) | ((d & 1) << 2);
}
__device__ __forceinline__ int bmoff(int m) {
    return (m << 10) | ((m & 1) << 6);
}

// ---------- real-core gate macros (G = [[ra, rb],[-rb, ra]]) ----------
#define LOADG(gi)                                                     \
    ulonglong2 g01 = *(const ulonglong2*)(gpkG + (gi) * 4);           \
    ulonglong2 g23 = *(const ulonglong2*)(gpkG + (gi) * 4 + 2);       \
    u64 RA = g01.x, RB = g01.y, RBm = g23.x, RBpm = g23.y;

#define PACKG(gi)                                                     \
    {                                                                 \
        LOADG(gi)                                                     \
        (void)RB; (void)RBm;                                          \
        _Pragma("unroll")                                             \
        for (int p = 0; p < 8; p++) {                                 \
            u64 R = Re[p], I = Im[p];                                 \
            Re[p] = f2fma(RBpm, f2swap(R), f2mul(RA, R));             \
            Im[p] = f2fma(RBpm, f2swap(I), f2mul(RA, I));             \
        }                                                             \
    }

#define REGPG(gi, mask)                                               \
    {                                                                 \
        LOADG(gi)                                                     \
        (void)RBpm;                                                   \
        _Pragma("unroll")                                             \
        for (int p0 = 0; p0 < 8; p0++) {                              \
            if (p0 & (mask)) continue;                                \
            const int p1 = p0 | (mask);                               \
            u64 aR = Re[p0], aI = Im[p0], bR = Re[p1], bI = Im[p1];   \
            Re[p0] = f2fma(RB, bR, f2mul(RA, aR));                    \
            Im[p0] = f2fma(RB, bI, f2mul(RA, aI));                    \
            Re[p1] = f2fma(RBm, aR, f2mul(RA, bR));                   \
            Im[p1] = f2fma(RBm, aI, f2mul(RA, bI));                   \
        }                                                             \
    }

#define SHUFG(gi, lm, mybit)                                          \
    {                                                                 \
        LOADG(gi)                                                     \
        (void)RBpm;                                                   \
        u64 Yo = (mybit) ? RBm : RB;                                  \
        _Pragma("unroll")                                             \
        for (int p = 0; p < 8; p++) {                                 \
            u64 mR = Re[p], mI = Im[p];                               \
            u64 oR = __shfl_xor_sync(0xffffffffu, mR, lm);            \
            u64 oI = __shfl_xor_sync(0xffffffffu, mI, lm);            \
            Re[p] = f2fma(Yo, oR, f2mul(RA, mR));                     \
            Im[p] = f2fma(Yo, oI, f2mul(RA, mI));                     \
        }                                                             \
    }

// diagonal passes
#define APPLY_SCALAR(sv)                                              \
    {                                                                 \
        u64 SX = pk((sv).x, (sv).x);                                  \
        u64 SY = pk((sv).y, (sv).y);                                  \
        u64 SYm = pk(-(sv).y, -(sv).y);                               \
        _Pragma("unroll")                                             \
        for (int p = 0; p < 8; p++) {                                 \
            u64 R = Re[p], I = Im[p];                                 \
            Re[p] = f2fma(SYm, I, f2mul(SX, R));                      \
            Im[p] = f2fma(SY, R, f2mul(SX, I));                       \
        }                                                             \
    }

#define APPLY_TAB(tabname, li)                                        \
    {                                                                 \
        _Pragma("unroll")                                             \
        for (int p = 0; p < 8; p++) {                                 \
            ulonglong2 dd = *(const ulonglong2*)&tabname[li][p][0];   \
            u64 DR = dd.x, DI = dd.y, DNI = tabname[li][p][2];        \
            u64 R = Re[p], I = Im[p];                                 \
            Re[p] = f2fma(DNI, I, f2mul(DR, R));                      \
            Im[p] = f2fma(DI, R, f2mul(DR, I));                       \
        }                                                             \
    }

__global__ __launch_bounds__(THREADS, 2)
void qgen_kernel(const float* __restrict__ noise,
                 const float* __restrict__ W1, const float* __restrict__ b1,
                 const float* __restrict__ W2, const float* __restrict__ b2,
                 const float* __restrict__ W3, const float* __restrict__ b3,
                 const float* __restrict__ W4, const float* __restrict__ b4,
                 float* __restrict__ out)
{
    __shared__ __align__(16) float exR[4096];
    __shared__ __align__(16) float exI[4096];
    __shared__ __align__(16) u64   gpkG[48 * 4];   // RA, RB, RBm, RBpm per gate
    __shared__ float2 s_rho[48];                   // right phase (on bit=1)
    __shared__ float2 s_lam[48];                   // left phase (on bit=1)
    __shared__ __align__(16) u64 LP1t[4][8][4];    // Δ1 local (ρ of B gates)
    __shared__ __align__(16) u64 LP2t[4][8][4];    // L_B local (λ of B gates)
    __shared__ __align__(16) u64 LPAt[4][8][4];    // R_A local (ρ of q11..q8)
    __shared__ float2 TS1t[3][256];                // Δ1 thread part (λ of A gates)
    __shared__ float2 TS2t[4][16];                 // R_A thread part (ρ of q7..q4)
    __shared__ float2 s_v[12][2];
    __shared__ float s_nz[12];
    __shared__ float s_h[64];
    __shared__ float s_par[NPAR];
    __shared__ float s_meas[12];
    __shared__ float s_wsum[8][12];
    __shared__ float s_h2[64];

    const int t   = threadIdx.x;
    const int bId = blockIdx.x;

    if (t < 12) s_nz[t] = noise[bId * 12 + t];
    __syncthreads();

    // ---- MLP1 ----
    if (t < 64) {
        float acc = b1[t];
        #pragma unroll
        for (int m = 0; m < 12; m++) acc += s_nz[m] * W1[m * 64 + t];
        s_h[t] = tanhf(acc);
    }
    __syncthreads();

    // ---- MLP2 ----
    if (t < NPAR) {
        float acc = b2[t];
        #pragma unroll 8
        for (int j = 0; j < 64; j++) acc += s_h[j] * W2[j * NPAR + t];
        s_par[t] = acc;
    }
    __syncthreads();

    // ---- per-gate: U = RZ RY RX = [[a,b],[-b*,a*]], a=gx+igy, b=gz+igw.
    // Factor U ~ diag(1, conj(c)conj(d)) * [[ra,rb],[-rb,ra]] * diag(1, d*conj(c)),
    // c = a/|a|, d = b/|b| (global phase dropped).
    if (t < 48) {
        float a = s_par[t * 3 + 0], b = s_par[t * 3 + 1], c = s_par[t * 3 + 2];
        float ca, sa, cb, sb, cc, sc;
        sincosf(0.5f * a, &sa, &ca);
        sincosf(0.5f * b, &sb, &cb);
        sincosf(0.5f * c, &sc, &cc);
        float x = cb * ca, y = sb * sa, z = sb * ca, w = cb * sa;
        float gx =  cc * x + sc * y;
        float gy =  cc * y - sc * x;
        float gz = -(cc * z + sc * w);
        float gw =  sc * z - cc * w;

        float ra = sqrtf(gx * gx + gy * gy);
        float rb = sqrtf(gz * gz + gw * gw);
        float cx, cyv, dx, dyv;
        if (ra > 1e-30f) { cx = gx / ra; cyv = gy / ra; } else { cx = 1.f; cyv = 0.f; }
        if (rb > 1e-30f) { dx = gz / rb; dyv = gw / rb; } else { dx = 1.f; dyv = 0.f; }

        s_rho[t] = make_float2(dx * cx + dyv * cyv, dyv * cx - dx * cyv);   // d*conj(c)
        s_lam[t] = make_float2(cx * dx - cyv * dyv, -(cx * dyv + cyv * dx)); // conj(c*d)

        u64* r = gpkG + t * 4;
        r[0] = pk(ra, ra);
        r[1] = pk(rb, rb);
        r[2] = pk(-rb, -rb);
        r[3] = pk(rb, -rb);

        if (t < 12) {   // layer-0 full gate: U|0> = (gx+igy, -(gz-igw))
            s_v[t][0] = make_float2(gx, gy);
            s_v[t][1] = make_float2(-gz, gw);
        }
    }
    __syncthreads();

    // ---- build diagonal tables ----
    // TS1[l][t] = prod over A-gate qubits q=11-b (thread bit b in layout B) of lambda
    #pragma unroll
    for (int l = 1; l <= 3; l++) {
        float2 acc = make_float2(1.f, 0.f);
        #pragma unroll
        for (int b = 0; b < 8; b++)
            if ((t >> b) & 1) acc = cm2(acc, s_lam[l * 12 + (11 - b)]);
        TS1t[l - 1][t] = acc;
    }
    // TS2[l][u] = prod over q=7-j (t bit j in layout A) of rho, l=1..3
    if (t < 48) {
        int l = (t >> 4) + 1, u = t & 15;
        float2 acc = make_float2(1.f, 0.f);
        #pragma unroll
        for (int j = 0; j < 4; j++)
            if ((u >> j) & 1) acc = cm2(acc, s_rho[l * 12 + (7 - j)]);
        TS2t[l][u] = acc;
    }
    // LP1 (rho, B gates) l=1..3 ; LPA (rho, q11..q8) l=1..3 : threads t<24
    if (t < 24) {
        int l = t / 8 + 1, r = t % 8;
        {   // LP1: reg bits r0->q2, r1->q1, r2->q0 ; lane -> q3
            float2 b0 = make_float2(1.f, 0.f);
            if (r & 1) b0 = cm2(b0, s_rho[l * 12 + 2]);
            if (r & 2) b0 = cm2(b0, s_rho[l * 12 + 1]);
            if (r & 4) b0 = cm2(b0, s_rho[l * 12 + 0]);
            float2 b1v = cm2(b0, s_rho[l * 12 + 3]);
            LP1t[l][r][0] = pk(b0.x, b1v.x);
            LP1t[l][r][1] = pk(b0.y, b1v.y);
            LP1t[l][r][2] = pk(-b0.y, -b1v.y);
        }
        {   // LPA: reg bits r0->q10, r1->q9, r2->q8 ; lane -> q11
            float2 b0 = make_float2(1.f, 0.f);
            if (r & 1) b0 = cm2(b0, s_rho[l * 12 + 10]);
            if (r & 2) b0 = cm2(b0, s_rho[l * 12 + 9]);
            if (r & 4) b0 = cm2(b0, s_rho[l * 12 + 8]);
            float2 b1v = cm2(b0, s_rho[l * 12 + 11]);
            LPAt[l][r][0] = pk(b0.x, b1v.x);
            LPAt[l][r][1] = pk(b0.y, b1v.y);
            LPAt[l][r][2] = pk(-b0.y, -b1v.y);
        }
    }
    // LP2 (lambda, B gates) l=1..2 : threads t<16
    if (t < 16) {
        int l = t / 8 + 1, r = t % 8;
        float2 b0 = make_float2(1.f, 0.f);
        if (r & 1) b0 = cm2(b0, s_lam[l * 12 + 2]);
        if (r & 2) b0 = cm2(b0, s_lam[l * 12 + 1]);
        if (r & 4) b0 = cm2(b0, s_lam[l * 12 + 0]);
        float2 b1v = cm2(b0, s_lam[l * 12 + 3]);
        LP2t[l][r][0] = pk(b0.x, b1v.x);
        LP2t[l][r][1] = pk(b0.y, b1v.y);
        LP2t[l][r][2] = pk(-b0.y, -b1v.y);
    }

    // ---- per-thread exchange addresses (round-6 layouts, unchanged) ----
    const int AbU = ((t >> 1) << 4) | (((t & 1) << 3) ^ ((t >> 1) & 15));
    const int uh  = t >> 5;
    const int Bb  = (uh << 7) | ((((t >> 1) & 15) ^ uh) << 3) | ((t & 1) << 2);
    const int puA = laddr(perm12(t));

    u64* exR64 = (u64*)exR;
    u64* exI64 = (u64*)exI;

    __syncthreads();   // tables + gpkG + s_v visible

    // ---- layer 0 (gates + first ring) via product-state synthesis ----
    u64 Re[8], Im[8];
    {
        c2 v[12][2];
        #pragma unroll
        for (int q = 0; q < 12; q++) {
            float2 a0 = s_v[q][0], a1 = s_v[q][1];
            v[q][0].r = a0.x; v[q][0].i = a0.y;
            v[q][1].r = a1.x; v[q][1].i = a1.y;
        }
        const int x2 = ((t >> 5) ^ (t >> 6)) & 1;
        const int x3 = ((t >> 4) ^ (t >> 5)) & 1;
        const int x4 = ((t >> 3) ^ (t >> 4)) & 1;
        const int x5 = ((t >> 2) ^ (t >> 3)) & 1;
        const int x6 = ((t >> 1) ^ (t >> 2)) & 1;
        const int x7 = ( t       ^ (t >> 1)) & 1;
        const int e0 = (t >> 7) & 1;
        const int e1 = ((t >> 6) ^ (t >> 7)) & 1;
        const int e4 = t & 1;

        c2 base = cmul(cmul(cmul(v[2][x2], v[3][x3]), cmul(v[4][x4], v[5][x5])),
                       cmul(v[6][x6], v[7][x7]));
        c2 base2[2];
        base2[0] = cmul(base, v[8][e4]);
        base2[1] = cmul(base, v[8][e4 ^ 1]);

        c2 A[2];
        A[0] = cmul(v[0][e0],     v[1][e1]);
        A[1] = cmul(v[0][e0 ^ 1], v[1][e1 ^ 1]);
        c2 B[4];
        B[0] = cmul(A[0], v[11][0]);
        B[1] = cmul(A[1], v[11][1]);
        B[2] = cmul(A[0], v[11][1]);
        B[3] = cmul(A[1], v[11][0]);
        c2 C[8];
        #pragma unroll
        for (int k2 = 0; k2 < 2; k2++)
            #pragma unroll
            for (int j = 0; j < 4; j++)
                C[k2 * 4 + j] = cmul(B[j], v[10][((j >> 1) & 1) ^ k2]);
        #pragma unroll
        for (int k3 = 0; k3 < 2; k3++)
            #pragma unroll
            for (int j = 0; j < 8; j += 2) {
                c2 d0 = cmul(cmul(C[j],     v[9][((j >> 2) & 1) ^ k3]), base2[k3]);
                c2 d1 = cmul(cmul(C[j + 1], v[9][(((j+1) >> 2) & 1) ^ k3]), base2[k3]);
                int p = (k3 * 8 + j) >> 1;
                Re[p] = pk(d0.r, d1.r);
                Im[p] = pk(d0.i, d1.i);
            }
    }

    // R_A(1): right phases of layer-1 A gates (post-synthesis, layout A)
    {
        float2 ts2 = TS2t[1][t & 15];
        APPLY_SCALAR(ts2)
        APPLY_TAB(LPAt, 1)
    }

    // ---- layers 1..3 ----
    #pragma unroll 1
    for (int l = 1; l < DEPTH; l++) {
        // A section (real cores): q11 pack, q10/q9/q8 regpair, q7..q4 shuffles
        PACKG(l * 12 + 11)
        REGPG(l * 12 + 10, 1)
        REGPG(l * 12 + 9, 2)
        REGPG(l * 12 + 8, 4)
        #pragma unroll
        for (int tb = 0; tb < 4; tb++) {
            SHUFG(l * 12 + 7 - tb, 1 << tb, (t >> tb) & 1)
        }

        // transpose A -> B
        __syncthreads();
        #pragma unroll
        for (int p = 0; p < 8; p++) {
            exR64[AbU ^ p] = Re[p];
            exI64[AbU ^ p] = Im[p];
        }
        __syncthreads();
        #pragma unroll
        for (int pB = 0; pB < 8; pB++) {
            const int a0 = Bb ^ bmoff(2 * pB);
            const int a1 = Bb ^ bmoff(2 * pB + 1);
            float r0 = *(const float*)((const char*)exR + a0);
            float r1 = *(const float*)((const char*)exR + a1);
            float i0 = *(const float*)((const char*)exI + a0);
            float i1 = *(const float*)((const char*)exI + a1);
            Re[pB] = pk(r0, r1);
            Im[pB] = pk(i0, i1);
        }

        // Δ1 = L_A · R_B (layout B: A qubits = thread bits, B qubits local)
        {
            float2 ts1 = TS1t[l - 1][t];
            APPLY_SCALAR(ts1)
            APPLY_TAB(LP1t, l)
        }

        // B section (real cores): q3 pack, q2/q1/q0 regpair
        PACKG(l * 12 + 3)
        REGPG(l * 12 + 2, 1)
        REGPG(l * 12 + 1, 2)
        REGPG(l * 12 + 0, 4)

        if (l == DEPTH - 1) break;   // L_B(3) dropped; ring folded into meas signs

        // L_B (left phases of B gates, local in layout B)
        APPLY_TAB(LP2t, l)

        // CNOT-ring permutation scatter, back to layout A
        __syncthreads();
        #pragma unroll
        for (int pB = 0; pB < 8; pB++) {
            float r0, r1, i0v, i1v;
            upk(Re[pB], r0, r1);
            upk(Im[pB], i0v, i1v);
            const int a0 = puA ^ laddr(perm12((2 * pB) << 8));
            const int a1 = puA ^ laddr(perm12((2 * pB + 1) << 8));
            *(float*)((char*)exR + a0) = r0;  *(float*)((char*)exI + a0) = i0v;
            *(float*)((char*)exR + a1) = r1;  *(float*)((char*)exI + a1) = i1v;
        }
        __syncthreads();
        #pragma unroll
        for (int p = 0; p < 8; p++) {
            Re[p] = exR64[AbU ^ p];
            Im[p] = exI64[AbU ^ p];
        }

        // R_A(l+1): right phases of next layer's A gates (layout A)
        {
            float2 ts2 = TS2t[l + 1][t & 15];
            APPLY_SCALAR(ts2)
            APPLY_TAB(LPAt, l + 1)
        }
    }

    // ---- <Z_q> in layout B with post-ring prefix-parity signs (round-6) ----
    float T0 = 0.f, T1 = 0.f, T2 = 0.f, T3 = 0.f;
    #pragma unroll
    for (int pB = 0; pB < 8; pB++) {
        u64 p2 = f2fma(Im[pB], Im[pB], f2mul(Re[pB], Re[pB]));
        float pl, ph; upk(p2, pl, ph);
        float sm = pl + ph, df = pl - ph;
        T0 += (__popc(pB & 3) & 1) ? -df : df;
        T1 += (__popc(pB & 6) & 1) ? -sm : sm;
        T2 += (__popc(pB & 7) & 1) ? -sm : sm;
        T3 += (__popc(pB & 7) & 1) ? -df : df;
    }
    float c[12];
    c[0] = (__popc(t) & 1) ? -T0 : T0;
    c[1] = T1; c[2] = T2; c[3] = T3;
    #pragma unroll
    for (int q = 4; q < 12; q++) {
        const int tmask = (0xFF << (11 - q)) & 0xFF;
        c[q] = (__popc(t & tmask) & 1) ? -T3 : T3;
    }

    #pragma unroll
    for (int s = 16; s >= 1; s >>= 1) {
        #pragma unroll
        for (int q = 0; q < 12; q++)
            c[q] += __shfl_xor_sync(0xffffffffu, c[q], s);
    }
    const int warp = t >> 5, lane = t & 31;
    if (lane == 0) {
        #pragma unroll
        for (int q = 0; q < 12; q++) s_wsum[warp][q] = c[q];
    }
    __syncthreads();
    if (t < 12) {
        float m = 0.f;
        #pragma unroll
        for (int w = 0; w < 8; w++) m += s_wsum[w][t];
        s_meas[t] = m;
    }
    __syncthreads();

    // ---- MLP3 ----
    if (t < 64) {
        float acc = b3[t];
        #pragma unroll
        for (int q = 0; q < 12; q++) acc += s_meas[q] * W3[q * 64 + t];
        s_h2[t] = tanhf(acc);
    }
    __syncthreads();

    // ---- out ----
    if (t < 2) {
        float acc = b4[t];
        #pragma unroll 8
        for (int j = 0; j < 64; j++) acc += s_h2[j] * W4[j * 2 + t];
        out[bId * 2 + t] = acc;
    }
}

extern "C" void kernel_launch(void* const* d_in, const int* in_sizes, int n_in,
                              void* d_out, int out_size)
{
    (void)n_in; (void)out_size;
    const float* noise = (const float*)d_in[0];
    const float* W1    = (const float*)d_in[1];
    const float* b1    = (const float*)d_in[2];
    const float* W2    = (const float*)d_in[3];
    const float* b2    = (const float*)d_in[4];
    const float* W3    = (const float*)d_in[5];
    const float* b3    = (const float*)d_in[6];
    const float* W4    = (const float*)d_in[7];
    const float* b4    = (const float*)d_in[8];
    float* out = (float*)d_out;

    const int B = in_sizes[0] / NQ;
    qgen_kernel<<<B, THREADS>>>(noise, W1, b1, W2, b2, W3, b3, W4, b4, out);
}

// round 12
// speedup vs baseline: 1.2422x; 1.0388x over previous
#include <cuda_runtime.h>

typedef unsigned long long u64;

#define NQ    12
#define DEPTH 4
#define NPAR  144
#define THREADS 256

// ---------- f32x2 packed helpers ----------
__device__ __forceinline__ u64 f2fma(u64 a, u64 b, u64 c) {
    u64 d; asm("fma.rn.f32x2 %0,%1,%2,%3;" : "=l"(d) : "l"(a), "l"(b), "l"(c)); return d;
}
__device__ __forceinline__ u64 f2mul(u64 a, u64 b) {
    u64 d; asm("mul.rn.f32x2 %0,%1,%2;" : "=l"(d) : "l"(a), "l"(b)); return d;
}
__device__ __forceinline__ u64 pk(float lo, float hi) {
    u64 r; asm("mov.b64 %0,{%1,%2};" : "=l"(r) : "f"(lo), "f"(hi)); return r;
}
__device__ __forceinline__ void upk(u64 v, float& lo, float& hi) {
    asm("mov.b64 {%0,%1},%2;" : "=f"(lo), "=f"(hi) : "l"(v));
}
__device__ __forceinline__ u64 f2swap(u64 v) {
    float lo, hi; upk(v, lo, hi); return pk(hi, lo);
}

struct c2 { float r, i; };
__device__ __forceinline__ c2 cmul(c2 a, c2 b) {
    c2 o; o.r = a.r * b.r - a.i * b.i; o.i = a.r * b.i + a.i * b.r; return o;
}
__device__ __forceinline__ float2 cm2(float2 a, float2 b) {
    return make_float2(a.x * b.x - a.y * b.y, a.x * b.y + a.y * b.x);
}

// ---------- CNOT-ring permutation (reference gate order) ----------
__device__ __forceinline__ int perm12(int s) {
    int d = s;
    #pragma unroll
    for (int q = 0; q < 12; q++) {
        int bc = 11 - q, bt = 11 - ((q + 1) % 12);
        d ^= ((d >> bc) & 1) << bt;
    }
    return d;
}
__device__ __forceinline__ int laddr(int d) {
    return ((d >> 5) << 7) | ((((d >> 1) & 15) ^ ((d >> 5) & 15)) << 3) | ((d & 1) << 2);
}
__device__ __forceinline__ int bmoff(int m) {
    return (m << 10) | ((m & 1) << 6);
}

// ---------- real-core gate macros (G = [[ra, rb],[-rb, ra]]) ----------
#define LOADG(gi)                                                     \
    ulonglong2 g01 = *(const ulonglong2*)(gpkG + (gi) * 4);           \
    ulonglong2 g23 = *(const ulonglong2*)(gpkG + (gi) * 4 + 2);       \
    u64 RA = g01.x, RB = g01.y, RBm = g23.x, RBpm = g23.y;

#define PACKG(gi)                                                     \
    {                                                                 \
        LOADG(gi)                                                     \
        (void)RB; (void)RBm;                                          \
        _Pragma("unroll")                                             \
        for (int p = 0; p < 8; p++) {                                 \
            u64 R = Re[p], I = Im[p];                                 \
            Re[p] = f2fma(RBpm, f2swap(R), f2mul(RA, R));             \
            Im[p] = f2fma(RBpm, f2swap(I), f2mul(RA, I));             \
        }                                                             \
    }

#define REGPG(gi, mask)                                               \
    {                                                                 \
        LOADG(gi)                                                     \
        (void)RBpm;                                                   \
        _Pragma("unroll")                                             \
        for (int p0 = 0; p0 < 8; p0++) {                              \
            if (p0 & (mask)) continue;                                \
            const int p1 = p0 | (mask);                               \
            u64 aR = Re[p0], aI = Im[p0], bR = Re[p1], bI = Im[p1];   \
            Re[p0] = f2fma(RB, bR, f2mul(RA, aR));                    \
            Im[p0] = f2fma(RB, bI, f2mul(RA, aI));                    \
            Re[p1] = f2fma(RBm, aR, f2mul(RA, bR));                   \
            Im[p1] = f2fma(RBm, aI, f2mul(RA, bI));                   \
        }                                                             \
    }

#define SHUFG(gi, lm, mybit)                                          \
    {                                                                 \
        LOADG(gi)                                                     \
        (void)RBpm;                                                   \
        u64 Yo = (mybit) ? RBm : RB;                                  \
        _Pragma("unroll")                                             \
        for (int p = 0; p < 8; p++) {                                 \
            u64 mR = Re[p], mI = Im[p];                               \
            u64 oR = __shfl_xor_sync(0xffffffffu, mR, lm);            \
            u64 oI = __shfl_xor_sync(0xffffffffu, mI, lm);            \
            Re[p] = f2fma(Yo, oR, f2mul(RA, mR));                     \
            Im[p] = f2fma(Yo, oI, f2mul(RA, mI));                     \
        }                                                             \
    }

// diagonal passes
#define APPLY_SCALAR(sv)                                              \
    {                                                                 \
        u64 SX = pk((sv).x, (sv).x);                                  \
        u64 SY = pk((sv).y, (sv).y);                                  \
        u64 SYm = pk(-(sv).y, -(sv).y);                               \
        _Pragma("unroll")                                             \
        for (int p = 0; p < 8; p++) {                                 \
            u64 R = Re[p], I = Im[p];                                 \
            Re[p] = f2fma(SYm, I, f2mul(SX, R));                      \
            Im[p] = f2fma(SY, R, f2mul(SX, I));                       \
        }                                                             \
    }

#define APPLY_TAB(tabname, li)                                        \
    {                                                                 \
        _Pragma("unroll")                                             \
        for (int p = 0; p < 8; p++) {                                 \
            ulonglong2 dd = *(const ulonglong2*)&tabname[li][p][0];   \
            u64 DR = dd.x, DI = dd.y, DNI = tabname[li][p][2];        \
            u64 R = Re[p], I = Im[p];                                 \
            Re[p] = f2fma(DNI, I, f2mul(DR, R));                      \
            Im[p] = f2fma(DI, R, f2mul(DR, I));                      \
        }                                                             \
    }

// one full layer body (LL = layer index, compile-time)
#define LAYER_BODY(LL, LAST)                                          \
    {                                                                 \
        PACKG((LL) * 12 + 11)                                         \
        REGPG((LL) * 12 + 10, 1)                                      \
        REGPG((LL) * 12 + 9, 2)                                       \
        REGPG((LL) * 12 + 8, 4)                                       \
        SHUFG((LL) * 12 + 7, 1, t & 1)                                \
        SHUFG((LL) * 12 + 6, 2, (t >> 1) & 1)                         \
        SHUFG((LL) * 12 + 5, 4, (t >> 2) & 1)                         \
        SHUFG((LL) * 12 + 4, 8, (t >> 3) & 1)                         \
        /* transpose A -> B */                                        \
        __syncthreads();                                              \
        _Pragma("unroll")                                             \
        for (int p = 0; p < 8; p++) {                                 \
            exR64[AbU ^ p] = Re[p];                                   \
            exI64[AbU ^ p] = Im[p];                                   \
        }                                                             \
        __syncthreads();                                              \
        _Pragma("unroll")                                             \
        for (int pB = 0; pB < 8; pB++) {                              \
            const int a0 = Bb ^ bmoff(2 * pB);                        \
            const int a1 = Bb ^ bmoff(2 * pB + 1);                    \
            float r0 = *(const float*)((const char*)exR + a0);        \
            float r1 = *(const float*)((const char*)exR + a1);        \
            float i0 = *(const float*)((const char*)exI + a0);        \
            float i1 = *(const float*)((const char*)exI + a1);        \
            Re[pB] = pk(r0, r1);                                      \
            Im[pB] = pk(i0, i1);                                      \
        }                                                             \
        /* Δ1 = L_A · R_B */                                          \
        {                                                             \
            float2 ts1 = TS1t[(LL) - 1][t];                           \
            APPLY_SCALAR(ts1)                                         \
            APPLY_TAB(LP1t, (LL))                                     \
        }                                                             \
        PACKG((LL) * 12 + 3)                                          \
        REGPG((LL) * 12 + 2, 1)                                       \
        REGPG((LL) * 12 + 1, 2)                                       \
        REGPG((LL) * 12 + 0, 4)                                       \
        if (!(LAST)) {                                                \
            /* L_B fused into perm scatter; back to layout A */       \
            __syncthreads();                                          \
            _Pragma("unroll")                                         \
            for (int pB = 0; pB < 8; pB++) {                          \
                ulonglong2 dd = *(const ulonglong2*)&LP2t[(LL)][pB][0]; \
                u64 DR = dd.x, DI = dd.y, DNI = LP2t[(LL)][pB][2];    \
                u64 R = Re[pB], I = Im[pB];                           \
                u64 Rn = f2fma(DNI, I, f2mul(DR, R));                 \
                u64 In = f2fma(DI, R, f2mul(DR, I));                  \
                float r0, r1, i0v, i1v;                               \
                upk(Rn, r0, r1);                                      \
                upk(In, i0v, i1v);                                    \
                const int a0 = puA ^ laddr(perm12((2 * pB) << 8));    \
                const int a1 = puA ^ laddr(perm12((2 * pB + 1) << 8)); \
                *(float*)((char*)exR + a0) = r0;                      \
                *(float*)((char*)exI + a0) = i0v;                     \
                *(float*)((char*)exR + a1) = r1;                      \
                *(float*)((char*)exI + a1) = i1v;                     \
            }                                                         \
            __syncthreads();                                          \
            _Pragma("unroll")                                         \
            for (int p = 0; p < 8; p++) {                             \
                Re[p] = exR64[AbU ^ p];                               \
                Im[p] = exI64[AbU ^ p];                               \
            }                                                         \
            /* R_A(LL+1) */                                           \
            {                                                         \
                float2 ts2 = TS2t[(LL) + 1][t & 15];                  \
                APPLY_SCALAR(ts2)                                     \
                APPLY_TAB(LPAt, (LL) + 1)                             \
            }                                                         \
        }                                                             \
    }

__global__ __launch_bounds__(THREADS, 2)
void qgen_kernel(const float* __restrict__ noise,
                 const float* __restrict__ W1, const float* __restrict__ b1,
                 const float* __restrict__ W2, const float* __restrict__ b2,
                 const float* __restrict__ W3, const float* __restrict__ b3,
                 const float* __restrict__ W4, const float* __restrict__ b4,
                 float* __restrict__ out)
{
    __shared__ __align__(16) float exR[4096];
    __shared__ __align__(16) float exI[4096];
    __shared__ __align__(16) u64   gpkG[48 * 4];   // RA, RB, RBm, RBpm per gate
    __shared__ float2 s_rho[48];                   // right phase (on bit=1)
    __shared__ float2 s_lam[48];                   // left phase (on bit=1)
    __shared__ __align__(16) u64 LP1t[4][8][4];    // Δ1 local (ρ of B gates)
    __shared__ __align__(16) u64 LP2t[4][8][4];    // L_B local (λ of B gates)
    __shared__ __align__(16) u64 LPAt[4][8][4];    // R_A local (ρ of q11..q8)
    __shared__ float2 TS1t[3][256];                // Δ1 thread part (λ of A gates)
    __shared__ float2 TS2t[4][16];                 // R_A thread part (ρ of q7..q4)
    __shared__ float2 s_v[12][2];
    __shared__ float s_nz[12];
    __shared__ float s_h[64];
    __shared__ float s_par[NPAR];
    __shared__ float s_meas[12];
    __shared__ float s_wsum[8][12];
    __shared__ float s_h2[64];

    const int t   = threadIdx.x;
    const int bId = blockIdx.x;

    if (t < 12) s_nz[t] = noise[bId * 12 + t];
    __syncthreads();

    // ---- MLP1 ----
    if (t < 64) {
        float acc = b1[t];
        #pragma unroll
        for (int m = 0; m < 12; m++) acc += s_nz[m] * W1[m * 64 + t];
        s_h[t] = tanhf(acc);
    }
    __syncthreads();

    // ---- MLP2 ----
    if (t < NPAR) {
        float acc = b2[t];
        #pragma unroll 8
        for (int j = 0; j < 64; j++) acc += s_h[j] * W2[j * NPAR + t];
        s_par[t] = acc;
    }
    __syncthreads();

    // ---- per-gate: U = RZ RY RX = [[a,b],[-b*,a*]], a=gx+igy, b=gz+igw.
    // U ~ diag(1, conj(c)conj(d)) * [[ra,rb],[-rb,ra]] * diag(1, d*conj(c))
    if (t < 48) {
        float a = s_par[t * 3 + 0], b = s_par[t * 3 + 1], c = s_par[t * 3 + 2];
        float ca, sa, cb, sb, cc, sc;
        sincosf(0.5f * a, &sa, &ca);
        sincosf(0.5f * b, &sb, &cb);
        sincosf(0.5f * c, &sc, &cc);
        float x = cb * ca, y = sb * sa, z = sb * ca, w = cb * sa;
        float gx =  cc * x + sc * y;
        float gy =  cc * y - sc * x;
        float gz = -(cc * z + sc * w);
        float gw =  sc * z - cc * w;

        float ra = sqrtf(gx * gx + gy * gy);
        float rb = sqrtf(gz * gz + gw * gw);
        float cx, cyv, dx, dyv;
        if (ra > 1e-30f) { cx = gx / ra; cyv = gy / ra; } else { cx = 1.f; cyv = 0.f; }
        if (rb > 1e-30f) { dx = gz / rb; dyv = gw / rb; } else { dx = 1.f; dyv = 0.f; }

        s_rho[t] = make_float2(dx * cx + dyv * cyv, dyv * cx - dx * cyv);
        s_lam[t] = make_float2(cx * dx - cyv * dyv, -(cx * dyv + cyv * dx));

        u64* r = gpkG + t * 4;
        r[0] = pk(ra, ra);
        r[1] = pk(rb, rb);
        r[2] = pk(-rb, -rb);
        r[3] = pk(rb, -rb);

        if (t < 12) {
            s_v[t][0] = make_float2(gx, gy);
            s_v[t][1] = make_float2(-gz, gw);
        }
    }
    __syncthreads();

    // ---- build diagonal tables ----
    #pragma unroll
    for (int l = 1; l <= 3; l++) {
        float2 acc = make_float2(1.f, 0.f);
        #pragma unroll
        for (int b = 0; b < 8; b++)
            if ((t >> b) & 1) acc = cm2(acc, s_lam[l * 12 + (11 - b)]);
        TS1t[l - 1][t] = acc;
    }
    if (t < 48) {
        int l = (t >> 4) + 1, u = t & 15;
        float2 acc = make_float2(1.f, 0.f);
        #pragma unroll
        for (int j = 0; j < 4; j++)
            if ((u >> j) & 1) acc = cm2(acc, s_rho[l * 12 + (7 - j)]);
        TS2t[l][u] = acc;
    }
    if (t < 24) {
        int l = t / 8 + 1, r = t % 8;
        {
            float2 b0 = make_float2(1.f, 0.f);
            if (r & 1) b0 = cm2(b0, s_rho[l * 12 + 2]);
            if (r & 2) b0 = cm2(b0, s_rho[l * 12 + 1]);
            if (r & 4) b0 = cm2(b0, s_rho[l * 12 + 0]);
            float2 b1v = cm2(b0, s_rho[l * 12 + 3]);
            LP1t[l][r][0] = pk(b0.x, b1v.x);
            LP1t[l][r][1] = pk(b0.y, b1v.y);
            LP1t[l][r][2] = pk(-b0.y, -b1v.y);
        }
        {
            float2 b0 = make_float2(1.f, 0.f);
            if (r & 1) b0 = cm2(b0, s_rho[l * 12 + 10]);
            if (r & 2) b0 = cm2(b0, s_rho[l * 12 + 9]);
            if (r & 4) b0 = cm2(b0, s_rho[l * 12 + 8]);
            float2 b1v = cm2(b0, s_rho[l * 12 + 11]);
            LPAt[l][r][0] = pk(b0.x, b1v.x);
            LPAt[l][r][1] = pk(b0.y, b1v.y);
            LPAt[l][r][2] = pk(-b0.y, -b1v.y);
        }
    }
    if (t < 16) {
        int l = t / 8 + 1, r = t % 8;
        float2 b0 = make_float2(1.f, 0.f);
        if (r & 1) b0 = cm2(b0, s_lam[l * 12 + 2]);
        if (r & 2) b0 = cm2(b0, s_lam[l * 12 + 1]);
        if (r & 4) b0 = cm2(b0, s_lam[l * 12 + 0]);
        float2 b1v = cm2(b0, s_lam[l * 12 + 3]);
        LP2t[l][r][0] = pk(b0.x, b1v.x);
        LP2t[l][r][1] = pk(b0.y, b1v.y);
        LP2t[l][r][2] = pk(-b0.y, -b1v.y);
    }

    // ---- per-thread exchange addresses ----
    const int AbU = ((t >> 1) << 4) | (((t & 1) << 3) ^ ((t >> 1) & 15));
    const int uh  = t >> 5;
    const int Bb  = (uh << 7) | ((((t >> 1) & 15) ^ uh) << 3) | ((t & 1) << 2);
    const int puA = laddr(perm12(t));

    u64* exR64 = (u64*)exR;
    u64* exI64 = (u64*)exI;

    __syncthreads();   // tables + gpkG + s_v visible

    // ---- layer 0 (gates + first ring) via product-state synthesis ----
    u64 Re[8], Im[8];
    {
        c2 v[12][2];
        #pragma unroll
        for (int q = 0; q < 12; q++) {
            float2 a0 = s_v[q][0], a1 = s_v[q][1];
            v[q][0].r = a0.x; v[q][0].i = a0.y;
            v[q][1].r = a1.x; v[q][1].i = a1.y;
        }
        const int x2 = ((t >> 5) ^ (t >> 6)) & 1;
        const int x3 = ((t >> 4) ^ (t >> 5)) & 1;
        const int x4 = ((t >> 3) ^ (t >> 4)) & 1;
        const int x5 = ((t >> 2) ^ (t >> 3)) & 1;
        const int x6 = ((t >> 1) ^ (t >> 2)) & 1;
        const int x7 = ( t       ^ (t >> 1)) & 1;
        const int e0 = (t >> 7) & 1;
        const int e1 = ((t >> 6) ^ (t >> 7)) & 1;
        const int e4 = t & 1;

        c2 base = cmul(cmul(cmul(v[2][x2], v[3][x3]), cmul(v[4][x4], v[5][x5])),
                       cmul(v[6][x6], v[7][x7]));
        c2 base2[2];
        base2[0] = cmul(base, v[8][e4]);
        base2[1] = cmul(base, v[8][e4 ^ 1]);

        c2 A[2];
        A[0] = cmul(v[0][e0],     v[1][e1]);
        A[1] = cmul(v[0][e0 ^ 1], v[1][e1 ^ 1]);
        c2 B[4];
        B[0] = cmul(A[0], v[11][0]);
        B[1] = cmul(A[1], v[11][1]);
        B[2] = cmul(A[0], v[11][1]);
        B[3] = cmul(A[1], v[11][0]);
        c2 C[8];
        #pragma unroll
        for (int k2 = 0; k2 < 2; k2++)
            #pragma unroll
            for (int j = 0; j < 4; j++)
                C[k2 * 4 + j] = cmul(B[j], v[10][((j >> 1) & 1) ^ k2]);
        #pragma unroll
        for (int k3 = 0; k3 < 2; k3++)
            #pragma unroll
            for (int j = 0; j < 8; j += 2) {
                c2 d0 = cmul(cmul(C[j],     v[9][((j >> 2) & 1) ^ k3]), base2[k3]);
                c2 d1 = cmul(cmul(C[j + 1], v[9][(((j+1) >> 2) & 1) ^ k3]), base2[k3]);
                int p = (k3 * 8 + j) >> 1;
                Re[p] = pk(d0.r, d1.r);
                Im[p] = pk(d0.i, d1.i);
            }
    }

    // R_A(1): right phases of layer-1 A gates (post-synthesis, layout A)
    {
        float2 ts2 = TS2t[1][t & 15];
        APPLY_SCALAR(ts2)
        APPLY_TAB(LPAt, 1)
    }

    // ---- layers 1..3 (fully unrolled; all table/perm indices compile-time) ----
    LAYER_BODY(1, false)
    LAYER_BODY(2, false)
    LAYER_BODY(3, true)

    // ---- <Z_q> in layout B with post-ring prefix-parity signs ----
    float T0 = 0.f, T1 = 0.f, T2 = 0.f, T3 = 0.f;
    #pragma unroll
    for (int pB = 0; pB < 8; pB++) {
        u64 p2 = f2fma(Im[pB], Im[pB], f2mul(Re[pB], Re[pB]));
        float pl, ph; upk(p2, pl, ph);
        float sm = pl + ph, df = pl - ph;
        T0 += (__popc(pB & 3) & 1) ? -df : df;
        T1 += (__popc(pB & 6) & 1) ? -sm : sm;
        T2 += (__popc(pB & 7) & 1) ? -sm : sm;
        T3 += (__popc(pB & 7) & 1) ? -df : df;
    }
    float c[12];
    c[0] = (__popc(t) & 1) ? -T0 : T0;
    c[1] = T1; c[2] = T2; c[3] = T3;
    #pragma unroll
    for (int q = 4; q < 12; q++) {
        const int tmask = (0xFF << (11 - q)) & 0xFF;
        c[q] = (__popc(t & tmask) & 1) ? -T3 : T3;
    }

    #pragma unroll
    for (int s = 16; s >= 1; s >>= 1) {
        #pragma unroll
        for (int q = 0; q < 12; q++)
            c[q] += __shfl_xor_sync(0xffffffffu, c[q], s);
    }
    const int warp = t >> 5, lane = t & 31;
    if (lane == 0) {
        #pragma unroll
        for (int q = 0; q < 12; q++) s_wsum[warp][q] = c[q];
    }
    __syncthreads();
    if (t < 12) {
        float m = 0.f;
        #pragma unroll
        for (int w = 0; w < 8; w++) m += s_wsum[w][t];
        s_meas[t] = m;
    }
    __syncthreads();

    // ---- MLP3 ----
    if (t < 64) {
        float acc = b3[t];
        #pragma unroll
        for (int q = 0; q < 12; q++) acc += s_meas[q] * W3[q * 64 + t];
        s_h2[t] = tanhf(acc);
    }
    __syncthreads();

    // ---- out ----
    if (t < 2) {
        float acc = b4[t];
        #pragma unroll 8
        for (int j = 0; j < 64; j++) acc += s_h2[j] * W4[j * 2 + t];
        out[bId * 2 + t] = acc;
    }
}

extern "C" void kernel_launch(void* const* d_in, const int* in_sizes, int n_in,
                              void* d_out, int out_size)
{
    (void)n_in; (void)out_size;
    const float* noise = (const float*)d_in[0];
    const float* W1    = (const float*)d_in[1];
    const float* b1    = (const float*)d_in[2];
    const float* W2    = (const float*)d_in[3];
    const float* b2    = (const float*)d_in[4];
    const float* W3    = (const float*)d_in[5];
    const float* b3    = (const float*)d_in[6];
    const float* W4    = (const float*)d_in[7];
    const float* b4    = (const float*)d_in[8];
    float* out = (float*)d_out;

    const int B = in_sizes[0] / NQ;
    qgen_kernel<<<B, THREADS>>>(noise, W1, b1, W2, b2, W3, b3, W4, b4, out);
}